// round 10
// baseline (speedup 1.0000x reference)
#include <cuda_runtime.h>
#include <cstdint>

#define DC 12                    // internal components
#define NSITE 32768              // 16*16*16*8
#define KMAT 144                 // 12x12
#define DIAGC 4.5f
#define SPB 16                   // sites per tile
#define NTHREADS (SPB * DC)      // 192
#define NBUF 8                   // pipeline depth == stages per tile
#define NTILE (NSITE / SPB)      // 2048 tiles
#define STAGE_FLTS (SPB * KMAT)                // 2304 floats per (re|im) plane
#define PLANE_BYTES (STAGE_FLTS * 4)           // 9216 B
#define STAGE_BYTES (PLANE_BYTES * 2)          // 18432 B (re+im)
#define SMEM_BYTES (NBUF * STAGE_BYTES)        // 147456 B -> 1 CTA per SM

__device__ __forceinline__ uint32_t s2u(const void* p) {
    return (uint32_t)__cvta_generic_to_shared(p);
}

__global__ __launch_bounds__(NTHREADS, 1)
void hop_kernel(const float* __restrict__ psi_re, const float* __restrict__ psi_im,
                const float* __restrict__ Kfr,    const float* __restrict__ Kfi,
                const float* __restrict__ Kbr,    const float* __restrict__ Kbi,
                float* __restrict__ out)
{
    extern __shared__ float kbuf[];              // [NBUF][2][STAGE_FLTS]
    __shared__ alignas(8) unsigned long long mbar[NBUF];

    const int tid = threadIdx.x;
    const unsigned s_loc = (unsigned)tid / DC;
    const unsigned irow  = (unsigned)tid % DC;

    // Contiguous tile range for this (persistent, 1-per-SM) CTA.
    const unsigned t0 = (unsigned)(((unsigned long long)blockIdx.x * NTILE) / gridDim.x);
    const unsigned t1 = (unsigned)(((unsigned long long)(blockIdx.x + 1) * NTILE) / gridDim.x);

    if (tid == 0) {
#pragma unroll
        for (int b = 0; b < NBUF; ++b)
            asm volatile("mbarrier.init.shared.b64 [%0], %1;" :: "r"(s2u(&mbar[b])), "r"(1));
        asm volatile("fence.proxy.async.shared::cta;" ::: "memory");
    }
    __syncthreads();

    // Producer: stage st = 2*mu + dir of tile `tile` into buffer st (NBUF==8).
    auto issue = [&](int st, unsigned tile) {
        const unsigned off = (((unsigned)(st >> 1)) * NSITE + tile * SPB) * KMAT;
        const float* srcR = ((st & 1) ? Kbr : Kfr) + off;
        const float* srcI = ((st & 1) ? Kbi : Kfi) + off;
        float* dstR = kbuf + st * (2 * STAGE_FLTS);
        float* dstI = dstR + STAGE_FLTS;
        const uint32_t mb = s2u(&mbar[st]);
        asm volatile("mbarrier.arrive.expect_tx.shared.b64 _, [%0], %1;"
                     :: "r"(mb), "r"((unsigned)STAGE_BYTES) : "memory");
        asm volatile("cp.async.bulk.shared::cta.global.mbarrier::complete_tx::bytes "
                     "[%0], [%1], %2, [%3];"
                     :: "r"(s2u(dstR)), "l"(srcR),
                        "r"((unsigned)PLANE_BYTES), "r"(mb) : "memory");
        asm volatile("cp.async.bulk.shared::cta.global.mbarrier::complete_tx::bytes "
                     "[%0], [%1], %2, [%3];"
                     :: "r"(s2u(dstI)), "l"(srcI),
                        "r"((unsigned)PLANE_BYTES), "r"(mb) : "memory");
    };

    // Prologue: fill the whole 8-deep pipeline with tile t0.
    if (tid == 0) {
#pragma unroll
        for (int st = 0; st < NBUF; ++st) issue(st, t0);
    }

    unsigned ph = 0;  // phase parity = (tile - t0) & 1
    for (unsigned tile = t0; tile < t1; ++tile, ph ^= 1) {
        const unsigned s = tile * SPB + s_loc;

        // Lattice coords and neighbor sites for this tile.
        const unsigned x = s & 7, y = (s >> 3) & 15, z = (s >> 7) & 15, t = (s >> 11) & 15;
        unsigned nb[8];   // [fwd_t, bwd_t, fwd_z, bwd_z, fwd_y, bwd_y, fwd_x, bwd_x]
        nb[0] = (s & ~(15u << 11)) | (((t + 1)  & 15) << 11);
        nb[1] = (s & ~(15u << 11)) | (((t + 15) & 15) << 11);
        nb[2] = (s & ~(15u << 7))  | (((z + 1)  & 15) << 7);
        nb[3] = (s & ~(15u << 7))  | (((z + 15) & 15) << 7);
        nb[4] = (s & ~(15u << 3))  | (((y + 1)  & 15) << 3);
        nb[5] = (s & ~(15u << 3))  | (((y + 15) & 15) << 3);
        const unsigned par = (t + z + y) & 1;
        nb[6] = par ? ((s & ~7u) | ((x + 1) & 7)) : s;   // mask_f: r==1
        nb[7] = par ? s : ((s & ~7u) | ((x + 7) & 7));   // mask_b: r==0

        float sr = 0.0f, si = 0.0f;

#pragma unroll
        for (int st = 0; st < 8; ++st) {
            // Prefetch neighbor psi vector (L1/L2-resident) BEFORE the TMA wait.
            const unsigned v = nb[st] * DC;
            const float4* vr4 = reinterpret_cast<const float4*>(psi_re + v);
            const float4* vi4 = reinterpret_cast<const float4*>(psi_im + v);
            const float4 c0 = vr4[0], c1 = vr4[1], c2 = vr4[2];
            const float4 d0 = vi4[0], d1 = vi4[1], d2 = vi4[2];

            // Wait for this stage's K tile.
            {
                const uint32_t mb = s2u(&mbar[st]);
                asm volatile(
                    "{\n\t.reg .pred P;\n\t"
                    "W%=:\n\t"
                    "mbarrier.try_wait.parity.shared.b64 P, [%0], %1;\n\t"
                    "@P bra D%=;\n\t"
                    "bra W%=;\n\t"
                    "D%=:\n\t}"
                    :: "r"(mb), "r"(ph) : "memory");
            }

            // Row dot-product from smem: conflict-free LDS.128 (48 B thread stride).
            const float* baseR = kbuf + st * (2 * STAGE_FLTS) + s_loc * KMAT + irow * DC;
            const float4* kr4 = reinterpret_cast<const float4*>(baseR);
            const float4* ki4 = reinterpret_cast<const float4*>(baseR + STAGE_FLTS);

            {
                float4 a = kr4[0], bb = ki4[0];
                sr = fmaf(a.x, c0.x, sr); sr = fmaf(-bb.x, d0.x, sr);
                si = fmaf(a.x, d0.x, si); si = fmaf( bb.x, c0.x, si);
                sr = fmaf(a.y, c0.y, sr); sr = fmaf(-bb.y, d0.y, sr);
                si = fmaf(a.y, d0.y, si); si = fmaf( bb.y, c0.y, si);
                sr = fmaf(a.z, c0.z, sr); sr = fmaf(-bb.z, d0.z, sr);
                si = fmaf(a.z, d0.z, si); si = fmaf( bb.z, c0.z, si);
                sr = fmaf(a.w, c0.w, sr); sr = fmaf(-bb.w, d0.w, sr);
                si = fmaf(a.w, d0.w, si); si = fmaf( bb.w, c0.w, si);
            }
            {
                float4 a = kr4[1], bb = ki4[1];
                sr = fmaf(a.x, c1.x, sr); sr = fmaf(-bb.x, d1.x, sr);
                si = fmaf(a.x, d1.x, si); si = fmaf( bb.x, c1.x, si);
                sr = fmaf(a.y, c1.y, sr); sr = fmaf(-bb.y, d1.y, sr);
                si = fmaf(a.y, d1.y, si); si = fmaf( bb.y, c1.y, si);
                sr = fmaf(a.z, c1.z, sr); sr = fmaf(-bb.z, d1.z, sr);
                si = fmaf(a.z, d1.z, si); si = fmaf( bb.z, c1.z, si);
                sr = fmaf(a.w, c1.w, sr); sr = fmaf(-bb.w, d1.w, sr);
                si = fmaf(a.w, d1.w, si); si = fmaf( bb.w, c1.w, si);
            }
            {
                float4 a = kr4[2], bb = ki4[2];
                sr = fmaf(a.x, c2.x, sr); sr = fmaf(-bb.x, d2.x, sr);
                si = fmaf(a.x, d2.x, si); si = fmaf( bb.x, c2.x, si);
                sr = fmaf(a.y, c2.y, sr); sr = fmaf(-bb.y, d2.y, sr);
                si = fmaf(a.y, d2.y, si); si = fmaf( bb.y, c2.y, si);
                sr = fmaf(a.z, c2.z, sr); sr = fmaf(-bb.z, d2.z, sr);
                si = fmaf(a.z, d2.z, si); si = fmaf( bb.z, c2.z, si);
                sr = fmaf(a.w, c2.w, sr); sr = fmaf(-bb.w, d2.w, sr);
                si = fmaf(a.w, d2.w, si); si = fmaf( bb.w, c2.w, si);
            }

            // Buffer st fully consumed -> refill with the next tile's same stage.
            __syncthreads();
            if (tid == 0 && tile + 1 < t1) issue(st, tile + 1);
        }

        const unsigned o = s * DC + irow;
        out[o]              = fmaf(-0.5f, sr, DIAGC * psi_re[o]);
        out[NSITE * DC + o] = fmaf(-0.5f, si, DIAGC * psi_im[o]);
    }
}

extern "C" void kernel_launch(void* const* d_in, const int* in_sizes, int n_in,
                              void* d_out, int out_size)
{
    const float* psi_re = (const float*)d_in[0];
    const float* psi_im = (const float*)d_in[1];
    const float* Kfr    = (const float*)d_in[2];
    const float* Kfi    = (const float*)d_in[3];
    const float* Kbr    = (const float*)d_in[4];
    const float* Kbi    = (const float*)d_in[5];
    float* out = (float*)d_out;

    // One persistent CTA per SM (smem footprint forces exclusivity).
    int dev = 0, nsm = 148;
    cudaGetDevice(&dev);
    cudaDeviceGetAttribute(&nsm, cudaDevAttrMultiProcessorCount, dev);

    cudaFuncSetAttribute(hop_kernel, cudaFuncAttributeMaxDynamicSharedMemorySize,
                         SMEM_BYTES);
    hop_kernel<<<nsm, NTHREADS, SMEM_BYTES>>>(
        psi_re, psi_im, Kfr, Kfi, Kbr, Kbi, out);
}

// round 12
// speedup vs baseline: 1.2091x; 1.2091x over previous
#include <cuda_runtime.h>
#include <cstdint>

#define DC 12                    // internal components
#define NSITE 32768              // 16*16*16*8
#define KMAT 144                 // 12x12
#define DIAGC 4.5f
#define SPB 16                   // sites per tile
#define NTHREADS (SPB * DC)      // 192
#define NBUF 3                   // pipeline depth (buffers)
#define CTAS_PER_SM 3
#define NTILE (NSITE / SPB)      // 2048 tiles
#define STAGE_FLTS (SPB * KMAT)                // 2304 floats per (re|im) plane
#define PLANE_BYTES (STAGE_FLTS * 4)           // 9216 B
#define STAGE_BYTES (PLANE_BYTES * 2)          // 18432 B (re+im)
#define SMEM_BYTES (NBUF * STAGE_BYTES)        // 55296 B -> 3 CTAs/SM (166 KB)

__device__ __forceinline__ uint32_t s2u(const void* p) {
    return (uint32_t)__cvta_generic_to_shared(p);
}

__global__ __launch_bounds__(NTHREADS, CTAS_PER_SM)
void hop_kernel(const float* __restrict__ psi_re, const float* __restrict__ psi_im,
                const float* __restrict__ Kfr,    const float* __restrict__ Kfi,
                const float* __restrict__ Kbr,    const float* __restrict__ Kbi,
                float* __restrict__ out)
{
    extern __shared__ float kbuf[];              // [NBUF][2][STAGE_FLTS]
    __shared__ alignas(8) unsigned long long mbar[NBUF];

    const int tid = threadIdx.x;
    const unsigned s_loc = (unsigned)tid / DC;
    const unsigned irow  = (unsigned)tid % DC;

    // Contiguous tile range for this persistent CTA (single wave, 3 CTAs/SM).
    const unsigned t0 = (unsigned)(((unsigned long long)blockIdx.x * NTILE) / gridDim.x);
    const unsigned t1 = (unsigned)(((unsigned long long)(blockIdx.x + 1) * NTILE) / gridDim.x);
    const unsigned total_stages = (t1 - t0) * 8u;

    if (tid == 0) {
#pragma unroll
        for (int b = 0; b < NBUF; ++b)
            asm volatile("mbarrier.init.shared.b64 [%0], %1;" :: "r"(s2u(&mbar[b])), "r"(1));
        asm volatile("fence.proxy.async.shared::cta;" ::: "memory");
    }
    __syncthreads();

    // Producer: global stage g -> (tile, st); buffer = g % NBUF.
    auto issue = [&](unsigned g) {
        const unsigned tile = t0 + (g >> 3);
        const int st = (int)(g & 7u);
        const int buf = (int)(g % NBUF);
        const unsigned off = (((unsigned)(st >> 1)) * NSITE + tile * SPB) * KMAT;
        const float* srcR = ((st & 1) ? Kbr : Kfr) + off;
        const float* srcI = ((st & 1) ? Kbi : Kfi) + off;
        float* dstR = kbuf + buf * (2 * STAGE_FLTS);
        float* dstI = dstR + STAGE_FLTS;
        const uint32_t mb = s2u(&mbar[buf]);
        asm volatile("mbarrier.arrive.expect_tx.shared.b64 _, [%0], %1;"
                     :: "r"(mb), "r"((unsigned)STAGE_BYTES) : "memory");
        asm volatile("cp.async.bulk.shared::cta.global.mbarrier::complete_tx::bytes "
                     "[%0], [%1], %2, [%3];"
                     :: "r"(s2u(dstR)), "l"(srcR),
                        "r"((unsigned)PLANE_BYTES), "r"(mb) : "memory");
        asm volatile("cp.async.bulk.shared::cta.global.mbarrier::complete_tx::bytes "
                     "[%0], [%1], %2, [%3];"
                     :: "r"(s2u(dstI)), "l"(srcI),
                        "r"((unsigned)PLANE_BYTES), "r"(mb) : "memory");
    };

    // Prologue: fill the pipeline.
    if (tid == 0) {
        issue(0); issue(1); issue(2);
    }

    unsigned g = 0;  // global stage counter (continuous across tiles)
    for (unsigned tile = t0; tile < t1; ++tile) {
        const unsigned s = tile * SPB + s_loc;

        // Lattice coords and neighbor sites for this tile.
        const unsigned x = s & 7, y = (s >> 3) & 15, z = (s >> 7) & 15, t = (s >> 11) & 15;
        unsigned nb[8];   // [fwd_t, bwd_t, fwd_z, bwd_z, fwd_y, bwd_y, fwd_x, bwd_x]
        nb[0] = (s & ~(15u << 11)) | (((t + 1)  & 15) << 11);
        nb[1] = (s & ~(15u << 11)) | (((t + 15) & 15) << 11);
        nb[2] = (s & ~(15u << 7))  | (((z + 1)  & 15) << 7);
        nb[3] = (s & ~(15u << 7))  | (((z + 15) & 15) << 7);
        nb[4] = (s & ~(15u << 3))  | (((y + 1)  & 15) << 3);
        nb[5] = (s & ~(15u << 3))  | (((y + 15) & 15) << 3);
        const unsigned par = (t + z + y) & 1;
        nb[6] = par ? ((s & ~7u) | ((x + 1) & 7)) : s;   // mask_f: r==1
        nb[7] = par ? s : ((s & ~7u) | ((x + 7) & 7));   // mask_b: r==0

        float sr = 0.0f, si = 0.0f;

#pragma unroll
        for (int st = 0; st < 8; ++st, ++g) {
            const int buf = (int)(g % NBUF);
            const unsigned ph = (g / NBUF) & 1u;

            // Prefetch neighbor psi vector (L1/L2-resident) BEFORE the TMA wait.
            const unsigned v = nb[st] * DC;
            const float4* vr4 = reinterpret_cast<const float4*>(psi_re + v);
            const float4* vi4 = reinterpret_cast<const float4*>(psi_im + v);
            const float4 c0 = vr4[0], c1 = vr4[1], c2 = vr4[2];
            const float4 d0 = vi4[0], d1 = vi4[1], d2 = vi4[2];

            // Wait for this stage's K tile.
            {
                const uint32_t mb = s2u(&mbar[buf]);
                asm volatile(
                    "{\n\t.reg .pred P;\n\t"
                    "W%=:\n\t"
                    "mbarrier.try_wait.parity.shared.b64 P, [%0], %1;\n\t"
                    "@P bra D%=;\n\t"
                    "bra W%=;\n\t"
                    "D%=:\n\t}"
                    :: "r"(mb), "r"(ph) : "memory");
            }

            // Row dot-product from smem: conflict-free LDS.128 (48 B thread stride).
            const float* baseR = kbuf + buf * (2 * STAGE_FLTS) + s_loc * KMAT + irow * DC;
            const float4* kr4 = reinterpret_cast<const float4*>(baseR);
            const float4* ki4 = reinterpret_cast<const float4*>(baseR + STAGE_FLTS);

            {
                float4 a = kr4[0], bb = ki4[0];
                sr = fmaf(a.x, c0.x, sr); sr = fmaf(-bb.x, d0.x, sr);
                si = fmaf(a.x, d0.x, si); si = fmaf( bb.x, c0.x, si);
                sr = fmaf(a.y, c0.y, sr); sr = fmaf(-bb.y, d0.y, sr);
                si = fmaf(a.y, d0.y, si); si = fmaf( bb.y, c0.y, si);
                sr = fmaf(a.z, c0.z, sr); sr = fmaf(-bb.z, d0.z, sr);
                si = fmaf(a.z, d0.z, si); si = fmaf( bb.z, c0.z, si);
                sr = fmaf(a.w, c0.w, sr); sr = fmaf(-bb.w, d0.w, sr);
                si = fmaf(a.w, d0.w, si); si = fmaf( bb.w, c0.w, si);
            }
            {
                float4 a = kr4[1], bb = ki4[1];
                sr = fmaf(a.x, c1.x, sr); sr = fmaf(-bb.x, d1.x, sr);
                si = fmaf(a.x, d1.x, si); si = fmaf( bb.x, c1.x, si);
                sr = fmaf(a.y, c1.y, sr); sr = fmaf(-bb.y, d1.y, sr);
                si = fmaf(a.y, d1.y, si); si = fmaf( bb.y, c1.y, si);
                sr = fmaf(a.z, c1.z, sr); sr = fmaf(-bb.z, d1.z, sr);
                si = fmaf(a.z, d1.z, si); si = fmaf( bb.z, c1.z, si);
                sr = fmaf(a.w, c1.w, sr); sr = fmaf(-bb.w, d1.w, sr);
                si = fmaf(a.w, d1.w, si); si = fmaf( bb.w, c1.w, si);
            }
            {
                float4 a = kr4[2], bb = ki4[2];
                sr = fmaf(a.x, c2.x, sr); sr = fmaf(-bb.x, d2.x, sr);
                si = fmaf(a.x, d2.x, si); si = fmaf( bb.x, c2.x, si);
                sr = fmaf(a.y, c2.y, sr); sr = fmaf(-bb.y, d2.y, sr);
                si = fmaf(a.y, d2.y, si); si = fmaf( bb.y, c2.y, si);
                sr = fmaf(a.z, c2.z, sr); sr = fmaf(-bb.z, d2.z, sr);
                si = fmaf(a.z, d2.z, si); si = fmaf( bb.z, c2.z, si);
                sr = fmaf(a.w, c2.w, sr); sr = fmaf(-bb.w, d2.w, sr);
                si = fmaf(a.w, d2.w, si); si = fmaf( bb.w, c2.w, si);
            }

            // Buffer fully consumed -> refill with stage g+NBUF (may cross tiles).
            __syncthreads();
            if (tid == 0 && g + NBUF < total_stages) issue(g + NBUF);
        }

        const unsigned o = s * DC + irow;
        out[o]              = fmaf(-0.5f, sr, DIAGC * psi_re[o]);
        out[NSITE * DC + o] = fmaf(-0.5f, si, DIAGC * psi_im[o]);
    }
}

extern "C" void kernel_launch(void* const* d_in, const int* in_sizes, int n_in,
                              void* d_out, int out_size)
{
    const float* psi_re = (const float*)d_in[0];
    const float* psi_im = (const float*)d_in[1];
    const float* Kfr    = (const float*)d_in[2];
    const float* Kfi    = (const float*)d_in[3];
    const float* Kbr    = (const float*)d_in[4];
    const float* Kbi    = (const float*)d_in[5];
    float* out = (float*)d_out;

    // Persistent single wave: 3 CTAs per SM.
    int dev = 0, nsm = 148;
    cudaGetDevice(&dev);
    cudaDeviceGetAttribute(&nsm, cudaDevAttrMultiProcessorCount, dev);

    cudaFuncSetAttribute(hop_kernel, cudaFuncAttributeMaxDynamicSharedMemorySize,
                         SMEM_BYTES);
    hop_kernel<<<nsm * CTAS_PER_SM, NTHREADS, SMEM_BYTES>>>(
        psi_re, psi_im, Kfr, Kfi, Kbr, Kbi, out);
}